// round 1
// baseline (speedup 1.0000x reference)
#include <cuda_runtime.h>
#include <math_constants.h>

// Paged attention decode, fp32.
// query:        [B=32, H=32, D=128]
// key_cache:    [NUM_PAGES=1024, PAGE_SIZE=16, H=32, D=128]
// value_cache:  same shape
// block_tables: [B, MAX_BLOCKS=64] int32
// context_lens: [B] int32
// out:          [B, H, D] fp32

#define NUM_HEADS 32
#define HEAD_DIM 128
#define PAGE_SZ 16
#define MAX_BLOCKS 64
#define NWARPS 8

__global__ __launch_bounds__(NWARPS * 32, 4)
void paged_attn_kernel(const float* __restrict__ q,
                       const float* __restrict__ kcache,
                       const float* __restrict__ vcache,
                       const int* __restrict__ btab,
                       const int* __restrict__ ctxlen,
                       float* __restrict__ out)
{
    const int h = blockIdx.x;          // head
    const int b = blockIdx.y;          // batch
    const int tid = threadIdx.x;
    const int wid = tid >> 5;
    const int lane = tid & 31;

    const int ctx = max(ctxlen[b], 1);

    const float scale = 0.08838834764831845f; // 1/sqrt(128)

    // Load this lane's 4 dims of q, pre-scaled.
    const float4 q4raw = *reinterpret_cast<const float4*>(
        q + ((size_t)(b * NUM_HEADS + h) * HEAD_DIM) + lane * 4);
    const float qx = q4raw.x * scale;
    const float qy = q4raw.y * scale;
    const float qz = q4raw.z * scale;
    const float qw = q4raw.w * scale;

    const int* bt = btab + b * MAX_BLOCKS;
    const int head_off = h * HEAD_DIM + lane * 4;

    float m = -CUDART_INF_F;
    float l = 0.0f;
    float ax = 0.0f, ay = 0.0f, az = 0.0f, aw = 0.0f;

    // Each warp strides over tokens.
    for (int t = wid; t < ctx; t += NWARPS) {
        const int page = __ldg(bt + (t >> 4));
        const size_t row = ((size_t)page * PAGE_SZ + (t & (PAGE_SZ - 1))) *
                           (NUM_HEADS * HEAD_DIM) + head_off;
        // Independent K and V loads issued back to back (MLP=2 per token).
        const float4 k4 = __ldg(reinterpret_cast<const float4*>(kcache + row));
        const float4 v4 = __ldg(reinterpret_cast<const float4*>(vcache + row));

        float s = qx * k4.x + qy * k4.y + qz * k4.z + qw * k4.w;
        #pragma unroll
        for (int o = 16; o > 0; o >>= 1)
            s += __shfl_xor_sync(0xffffffff, s, o);

        const float mnew = fmaxf(m, s);
        const float alpha = __expf(m - mnew);   // 0 on first iter (m=-inf)
        const float p = __expf(s - mnew);
        l = l * alpha + p;
        ax = ax * alpha + p * v4.x;
        ay = ay * alpha + p * v4.y;
        az = az * alpha + p * v4.z;
        aw = aw * alpha + p * v4.w;
        m = mnew;
    }

    // Cross-warp merge.
    __shared__ float sm_m[NWARPS];
    __shared__ float sm_l[NWARPS];
    __shared__ float sm_acc[NWARPS][HEAD_DIM];

    if (lane == 0) { sm_m[wid] = m; sm_l[wid] = l; }
    sm_acc[wid][lane * 4 + 0] = ax;
    sm_acc[wid][lane * 4 + 1] = ay;
    sm_acc[wid][lane * 4 + 2] = az;
    sm_acc[wid][lane * 4 + 3] = aw;
    __syncthreads();

    if (tid < HEAD_DIM) {
        float gm = -CUDART_INF_F;
        #pragma unroll
        for (int w = 0; w < NWARPS; w++) gm = fmaxf(gm, sm_m[w]);
        // ctx >= 1 guarantees warp 0 processed token 0, so gm is finite.
        float gl = 0.0f, ga = 0.0f;
        #pragma unroll
        for (int w = 0; w < NWARPS; w++) {
            const float f = __expf(sm_m[w] - gm); // 0 for warps with no tokens
            gl += f * sm_l[w];
            ga += f * sm_acc[w][tid];
        }
        out[(size_t)(b * NUM_HEADS + h) * HEAD_DIM + tid] = ga / gl;
    }
}

extern "C" void kernel_launch(void* const* d_in, const int* in_sizes, int n_in,
                              void* d_out, int out_size)
{
    const float* q      = (const float*)d_in[0];
    const float* kcache = (const float*)d_in[1];
    const float* vcache = (const float*)d_in[2];
    const int*   btab   = (const int*)d_in[3];
    const int*   clen   = (const int*)d_in[4];
    float* out = (float*)d_out;

    const int B = in_sizes[4];              // context_lens has B elements
    dim3 grid(NUM_HEADS, B);
    dim3 block(NWARPS * 32);
    paged_attn_kernel<<<grid, block>>>(q, kcache, vcache, btab, clen, out);
}

// round 2
// speedup vs baseline: 1.2325x; 1.2325x over previous
#include <cuda_runtime.h>
#include <math_constants.h>

// Paged attention decode, fp32.
// query:        [B=32, H=32, D=128]
// key_cache:    [NUM_PAGES=1024, PAGE_SIZE=16, H=32, D=128]
// value_cache:  same shape
// block_tables: [B, MAX_BLOCKS=64] int32
// context_lens: [B] int32
// out:          [B, H, D] fp32

#define NUM_HEADS 32
#define HEAD_DIM 128
#define PAGE_SZ 16
#define MAX_BLOCKS 64
#define NWARPS 8
#define UNROLL 4

__global__ __launch_bounds__(NWARPS * 32, 3)
void paged_attn_kernel(const float* __restrict__ q,
                       const float* __restrict__ kcache,
                       const float* __restrict__ vcache,
                       const int* __restrict__ btab,
                       const int* __restrict__ ctxlen,
                       float* __restrict__ out)
{
    const int h = blockIdx.x;          // head
    const int b = blockIdx.y;          // batch
    const int tid = threadIdx.x;
    const int wid = tid >> 5;
    const int lane = tid & 31;

    const int ctx = max(ctxlen[b], 1);

    const float scale = 0.08838834764831845f; // 1/sqrt(128)

    // Load this lane's 4 dims of q, pre-scaled.
    const float4 q4raw = *reinterpret_cast<const float4*>(
        q + ((size_t)(b * NUM_HEADS + h) * HEAD_DIM) + lane * 4);
    const float qx = q4raw.x * scale;
    const float qy = q4raw.y * scale;
    const float qz = q4raw.z * scale;
    const float qw = q4raw.w * scale;

    const int* bt = btab + b * MAX_BLOCKS;
    const int head_off = h * HEAD_DIM + lane * 4;

    float m = -CUDART_INF_F;
    float l = 0.0f;
    float ax = 0.0f, ay = 0.0f, az = 0.0f, aw = 0.0f;

    // Each warp takes groups of UNROLL consecutive tokens, strided by the
    // 8 warps: high MLP (8 independent LDG.128 in flight per iteration).
    for (int t = wid * UNROLL; t < ctx; t += NWARPS * UNROLL) {
        float4 k4[UNROLL], v4[UNROLL];
        #pragma unroll
        for (int j = 0; j < UNROLL; j++) {
            const int tt = min(t + j, ctx - 1);     // clamp: always a valid row
            const int page = __ldg(bt + (tt >> 4));
            const size_t row = ((size_t)page * PAGE_SZ + (tt & (PAGE_SZ - 1))) *
                               (NUM_HEADS * HEAD_DIM) + head_off;
            k4[j] = __ldcs(reinterpret_cast<const float4*>(kcache + row));
            v4[j] = __ldcs(reinterpret_cast<const float4*>(vcache + row));
        }

        float s[UNROLL];
        #pragma unroll
        for (int j = 0; j < UNROLL; j++)
            s[j] = qx * k4[j].x + qy * k4[j].y + qz * k4[j].z + qw * k4[j].w;

        // 4 independent butterfly reductions, interleaved for ILP.
        #pragma unroll
        for (int o = 16; o > 0; o >>= 1) {
            #pragma unroll
            for (int j = 0; j < UNROLL; j++)
                s[j] += __shfl_xor_sync(0xffffffff, s[j], o);
        }

        #pragma unroll
        for (int j = 0; j < UNROLL; j++)
            if (t + j >= ctx) s[j] = -CUDART_INF_F;

        const float smax = fmaxf(fmaxf(s[0], s[1]), fmaxf(s[2], s[3]));
        const float mnew = fmaxf(m, smax);          // finite: s[0] always valid
        const float alpha = __expf(m - mnew);       // 0 on first iter

        float p[UNROLL];
        #pragma unroll
        for (int j = 0; j < UNROLL; j++)
            p[j] = __expf(s[j] - mnew);             // 0 for masked lanes

        l = l * alpha + ((p[0] + p[1]) + (p[2] + p[3]));
        ax = ax * alpha + p[0] * v4[0].x + p[1] * v4[1].x + p[2] * v4[2].x + p[3] * v4[3].x;
        ay = ay * alpha + p[0] * v4[0].y + p[1] * v4[1].y + p[2] * v4[2].y + p[3] * v4[3].y;
        az = az * alpha + p[0] * v4[0].z + p[1] * v4[1].z + p[2] * v4[2].z + p[3] * v4[3].z;
        aw = aw * alpha + p[0] * v4[0].w + p[1] * v4[1].w + p[2] * v4[2].w + p[3] * v4[3].w;
        m = mnew;
    }

    // Cross-warp merge.
    __shared__ float sm_m[NWARPS];
    __shared__ float sm_l[NWARPS];
    __shared__ float sm_acc[NWARPS][HEAD_DIM];

    if (lane == 0) { sm_m[wid] = m; sm_l[wid] = l; }
    sm_acc[wid][lane * 4 + 0] = ax;
    sm_acc[wid][lane * 4 + 1] = ay;
    sm_acc[wid][lane * 4 + 2] = az;
    sm_acc[wid][lane * 4 + 3] = aw;
    __syncthreads();

    if (tid < HEAD_DIM) {
        float gm = -CUDART_INF_F;
        #pragma unroll
        for (int w = 0; w < NWARPS; w++) gm = fmaxf(gm, sm_m[w]);
        // ctx >= 1 guarantees warp 0 processed token 0, so gm is finite.
        float gl = 0.0f, ga = 0.0f;
        #pragma unroll
        for (int w = 0; w < NWARPS; w++) {
            const float f = __expf(sm_m[w] - gm); // 0 for warps with no tokens
            gl += f * sm_l[w];
            ga += f * sm_acc[w][tid];
        }
        out[(size_t)(b * NUM_HEADS + h) * HEAD_DIM + tid] = ga / gl;
    }
}

extern "C" void kernel_launch(void* const* d_in, const int* in_sizes, int n_in,
                              void* d_out, int out_size)
{
    const float* q      = (const float*)d_in[0];
    const float* kcache = (const float*)d_in[1];
    const float* vcache = (const float*)d_in[2];
    const int*   btab   = (const int*)d_in[3];
    const int*   clen   = (const int*)d_in[4];
    float* out = (float*)d_out;

    const int B = in_sizes[4];              // context_lens has B elements
    dim3 grid(NUM_HEADS, B);
    dim3 block(NWARPS * 32);
    paged_attn_kernel<<<grid, block>>>(q, kcache, vcache, btab, clen, out);
}

// round 3
// speedup vs baseline: 1.3069x; 1.0603x over previous
#include <cuda_runtime.h>
#include <math_constants.h>

// Paged attention decode, fp32, split-KV (2 kernels: partial + merge).
// query:        [B=32, H=32, D=128]
// key_cache:    [NUM_PAGES=1024, PAGE_SIZE=16, H=32, D=128]
// value_cache:  same shape
// block_tables: [B, MAX_BLOCKS=64] int32
// context_lens: [B] int32
// out:          [B, H, D] fp32

#define NUM_HEADS 32
#define HEAD_DIM 128
#define PAGE_SZ 16
#define MAX_BLOCKS 64
#define NWARPS 8
#define UNROLL 4
#define NSPLIT 4
#define MAXB 32

// Scratch for split-KV partials (allocation-free: __device__ globals).
__device__ float g_part_m[MAXB * NUM_HEADS * NSPLIT];
__device__ float g_part_l[MAXB * NUM_HEADS * NSPLIT];
__device__ float g_part_acc[MAXB * NUM_HEADS * NSPLIT * HEAD_DIM];

__global__ __launch_bounds__(NWARPS * 32, 3)
void paged_attn_partial(const float* __restrict__ q,
                        const float* __restrict__ kcache,
                        const float* __restrict__ vcache,
                        const int* __restrict__ btab,
                        const int* __restrict__ ctxlen)
{
    const int h = blockIdx.x;          // head
    const int b = blockIdx.y;          // batch
    const int split = blockIdx.z;      // KV split
    const int tid = threadIdx.x;
    const int wid = tid >> 5;
    const int lane = tid & 31;

    const int ctx = max(ctxlen[b], 1);
    const int chunk = (ctx + NSPLIT - 1) / NSPLIT;
    const int t0 = split * chunk;
    const int t1 = min(t0 + chunk, ctx);

    const int pidx = (b * NUM_HEADS + h) * NSPLIT + split;
    float* pacc = g_part_acc + (size_t)pidx * HEAD_DIM;

    if (t0 >= t1) {
        // Empty split: write neutral element.
        if (tid == 0) { g_part_m[pidx] = -CUDART_INF_F; g_part_l[pidx] = 0.0f; }
        if (tid < HEAD_DIM) pacc[tid] = 0.0f;
        return;
    }

    const float scale = 0.08838834764831845f; // 1/sqrt(128)

    const float4 q4raw = *reinterpret_cast<const float4*>(
        q + ((size_t)(b * NUM_HEADS + h) * HEAD_DIM) + lane * 4);
    const float qx = q4raw.x * scale;
    const float qy = q4raw.y * scale;
    const float qz = q4raw.z * scale;
    const float qw = q4raw.w * scale;

    const int* bt = btab + b * MAX_BLOCKS;
    const int head_off = h * HEAD_DIM + lane * 4;

    float m = -CUDART_INF_F;
    float l = 0.0f;
    float ax = 0.0f, ay = 0.0f, az = 0.0f, aw = 0.0f;

    // Each warp takes groups of UNROLL consecutive tokens in [t0, t1).
    for (int t = t0 + wid * UNROLL; t < t1; t += NWARPS * UNROLL) {
        float4 k4[UNROLL], v4[UNROLL];
        #pragma unroll
        for (int j = 0; j < UNROLL; j++) {
            const int tt = min(t + j, t1 - 1);      // clamp: always a valid row
            const int page = __ldg(bt + (tt >> 4));
            const size_t row = ((size_t)page * PAGE_SZ + (tt & (PAGE_SZ - 1))) *
                               (NUM_HEADS * HEAD_DIM) + head_off;
            k4[j] = __ldcs(reinterpret_cast<const float4*>(kcache + row));
            v4[j] = __ldcs(reinterpret_cast<const float4*>(vcache + row));
        }

        float s[UNROLL];
        #pragma unroll
        for (int j = 0; j < UNROLL; j++)
            s[j] = qx * k4[j].x + qy * k4[j].y + qz * k4[j].z + qw * k4[j].w;

        #pragma unroll
        for (int o = 16; o > 0; o >>= 1) {
            #pragma unroll
            for (int j = 0; j < UNROLL; j++)
                s[j] += __shfl_xor_sync(0xffffffff, s[j], o);
        }

        #pragma unroll
        for (int j = 0; j < UNROLL; j++)
            if (t + j >= t1) s[j] = -CUDART_INF_F;

        const float smax = fmaxf(fmaxf(s[0], s[1]), fmaxf(s[2], s[3]));
        const float mnew = fmaxf(m, smax);          // finite: s[0] always valid
        const float alpha = __expf(m - mnew);       // 0 on first iter

        float p[UNROLL];
        #pragma unroll
        for (int j = 0; j < UNROLL; j++)
            p[j] = __expf(s[j] - mnew);             // 0 for masked lanes

        l = l * alpha + ((p[0] + p[1]) + (p[2] + p[3]));
        ax = ax * alpha + p[0] * v4[0].x + p[1] * v4[1].x + p[2] * v4[2].x + p[3] * v4[3].x;
        ay = ay * alpha + p[0] * v4[0].y + p[1] * v4[1].y + p[2] * v4[2].y + p[3] * v4[3].y;
        az = az * alpha + p[0] * v4[0].z + p[1] * v4[1].z + p[2] * v4[2].z + p[3] * v4[3].z;
        aw = aw * alpha + p[0] * v4[0].w + p[1] * v4[1].w + p[2] * v4[2].w + p[3] * v4[3].w;
        m = mnew;
    }

    // Cross-warp merge within CTA, then write partial.
    __shared__ float sm_m[NWARPS];
    __shared__ float sm_l[NWARPS];
    __shared__ float sm_acc[NWARPS][HEAD_DIM];

    if (lane == 0) { sm_m[wid] = m; sm_l[wid] = l; }
    sm_acc[wid][lane * 4 + 0] = ax;
    sm_acc[wid][lane * 4 + 1] = ay;
    sm_acc[wid][lane * 4 + 2] = az;
    sm_acc[wid][lane * 4 + 3] = aw;
    __syncthreads();

    if (tid < HEAD_DIM) {
        float gm = -CUDART_INF_F;
        #pragma unroll
        for (int w = 0; w < NWARPS; w++) gm = fmaxf(gm, sm_m[w]);
        // t1 > t0 guarantees warp 0 processed at least one token -> gm finite.
        float gl = 0.0f, ga = 0.0f;
        #pragma unroll
        for (int w = 0; w < NWARPS; w++) {
            const float f = __expf(sm_m[w] - gm); // 0 for warps with no tokens
            gl += f * sm_l[w];
            ga += f * sm_acc[w][tid];
        }
        if (tid == 0) { g_part_m[pidx] = gm; g_part_l[pidx] = gl; }
        pacc[tid] = ga;
        if (tid == 1) g_part_l[pidx] = gl;      // redundant-safe; keep single writer below
    }
}

__global__ __launch_bounds__(HEAD_DIM)
void paged_attn_merge(float* __restrict__ out)
{
    const int bh = blockIdx.x;                  // b * NUM_HEADS + h
    const int tid = threadIdx.x;                // dim

    const int base = bh * NSPLIT;

    float gm = -CUDART_INF_F;
    #pragma unroll
    for (int s = 0; s < NSPLIT; s++) gm = fmaxf(gm, g_part_m[base + s]);

    float gl = 0.0f, ga = 0.0f;
    #pragma unroll
    for (int s = 0; s < NSPLIT; s++) {
        const float f = __expf(g_part_m[base + s] - gm);  // 0 for empty splits
        gl += f * g_part_l[base + s];
        ga += f * g_part_acc[(size_t)(base + s) * HEAD_DIM + tid];
    }
    out[(size_t)bh * HEAD_DIM + tid] = ga / gl;
}

extern "C" void kernel_launch(void* const* d_in, const int* in_sizes, int n_in,
                              void* d_out, int out_size)
{
    const float* q      = (const float*)d_in[0];
    const float* kcache = (const float*)d_in[1];
    const float* vcache = (const float*)d_in[2];
    const int*   btab   = (const int*)d_in[3];
    const int*   clen   = (const int*)d_in[4];
    float* out = (float*)d_out;

    const int B = in_sizes[4];              // context_lens has B elements

    dim3 grid(NUM_HEADS, B, NSPLIT);
    dim3 block(NWARPS * 32);
    paged_attn_partial<<<grid, block>>>(q, kcache, vcache, btab, clen);

    paged_attn_merge<<<B * NUM_HEADS, HEAD_DIM>>>(out);
}